// round 2
// baseline (speedup 1.0000x reference)
#include <cuda_runtime.h>

#define NROWS 4096
#define DIM   2048
#define NC    128
#define NTILE 4            // column tiles in k_mean (512 cols each)
#define KZ    64           // K-chunks in gram
#define KCH   32           // chunk size, KZ*KCH == DIM
#define MARGIN 0.5f

// ---------------- persistent scratch (static device globals; no allocs) ----
__device__ int   g_order[NROWS];
__device__ int   g_start[NC];
__device__ int   g_count[NC];
__device__ float g_meanR[NC * DIM];
__device__ float g_meanT[NC * DIM];
__device__ float g_cent [NC * DIM];
__device__ float g_npart[3][NC][NTILE];   // [0]=|meanR|^2 parts, [1]=|meanT|^2, [2]=|cent|^2
__device__ float g_S1p[KZ][NC * NC];      // meanR . cent^T partials per k-chunk
__device__ float g_S2p[KZ][NC * NC];      // meanT . cent^T partials per k-chunk
__device__ float g_lpart[64];

// ---------------- small float4 helpers ------------------------------------
__device__ __forceinline__ float4 f4add(float4 a, float4 b) {
    return make_float4(a.x + b.x, a.y + b.y, a.z + b.z, a.w + b.w);
}
__device__ __forceinline__ float4 f4scale(float4 a, float s) {
    return make_float4(a.x * s, a.y * s, a.z * s, a.w * s);
}
__device__ __forceinline__ float f4dot(float4 a, float4 b) {
    return a.x * b.x + a.y * b.y + a.z * b.z + a.w * b.w;
}

// ---------------- Kernel 1: deterministic stable counting sort ------------
// One block, 1024 threads (32 warps). Warp w owns elements [w*128, w*128+128).
// Per-chunk stable ranks via __match_any_sync; chunk histograms; per-class
// chunk prefix; class prefix; scatter. Fully deterministic permutation.
__global__ void __launch_bounds__(1024) k_sort(const int* __restrict__ tgt) {
    __shared__ int hist[32][NC];
    __shared__ int totals[NC];
    __shared__ int cinc[NC];
    int tid = threadIdx.x;
    for (int i = tid; i < 32 * NC; i += 1024) (&hist[0][0])[i] = 0;
    __syncthreads();

    int w = tid >> 5, lane = tid & 31;
    int myc[4], myr[4];
#pragma unroll
    for (int s = 0; s < 4; s++) {
        int idx = w * 128 + s * 32 + lane;
        int c = tgt[idx];
        unsigned mk = __match_any_sync(0xffffffffu, c);
        int leader = __ffs(mk) - 1;
        int lr = __popc(mk & ((1u << lane) - 1u));
        int prev = hist[w][c];
        __syncwarp();
        if (lane == leader) hist[w][c] = prev + __popc(mk);
        __syncwarp();
        myc[s] = c;
        myr[s] = prev + lr;
    }
    __syncthreads();

    // per-class exclusive prefix over the 32 chunks; totals per class
    if (tid < NC) {
        int run = 0;
#pragma unroll 4
        for (int k = 0; k < 32; k++) {
            int v = hist[k][tid];
            hist[k][tid] = run;
            run += v;
        }
        totals[tid] = run;
        cinc[tid] = run;
    }
    __syncthreads();

    // inclusive scan over classes (Hillis-Steele)
    for (int off = 1; off < NC; off <<= 1) {
        int v = 0;
        if (tid < NC && tid >= off) v = cinc[tid - off];
        __syncthreads();
        if (tid < NC) cinc[tid] += v;
        __syncthreads();
    }
    if (tid < NC) {
        g_start[tid] = cinc[tid] - totals[tid];
        g_count[tid] = totals[tid];
    }

    // scatter (all shared values finalized behind the last __syncthreads)
#pragma unroll
    for (int s = 0; s < 4; s++) {
        int c = myc[s];
        int pos = (cinc[c] - totals[c]) + hist[w][c] + myr[s];
        g_order[pos] = w * 128 + s * 32 + lane;
    }
}

// ---------------- Kernel 2: per-class means + centers + norm partials -----
// Grid (NC, NTILE), 128 threads. Each thread owns 4 columns (float4).
// Register accumulation over the class's rows in fixed order: deterministic,
// no atomics. Unroll-4 over rows -> 8 independent 16B loads in flight per
// thread to sit on the HBM bandwidth asymptote. Dominant cost: 64 MB reads.
__global__ void __launch_bounds__(128) k_mean(const float* __restrict__ m1,
                                              const float* __restrict__ m2) {
    int c = blockIdx.x;
    int tile = blockIdx.y;
    int col = tile * 512 + threadIdx.x * 4;
    int start = g_start[c];
    int cnt = g_count[c];

    float4 sR = make_float4(0.f, 0.f, 0.f, 0.f);
    float4 sT = make_float4(0.f, 0.f, 0.f, 0.f);

    int r = 0;
    for (; r + 4 <= cnt; r += 4) {
        int r0 = __ldg(&g_order[start + r]);
        int r1 = __ldg(&g_order[start + r + 1]);
        int r2 = __ldg(&g_order[start + r + 2]);
        int r3 = __ldg(&g_order[start + r + 3]);
        float4 a0 = __ldg((const float4*)(m1 + r0 * DIM + col));
        float4 b0 = __ldg((const float4*)(m2 + r0 * DIM + col));
        float4 a1 = __ldg((const float4*)(m1 + r1 * DIM + col));
        float4 b1 = __ldg((const float4*)(m2 + r1 * DIM + col));
        float4 a2 = __ldg((const float4*)(m1 + r2 * DIM + col));
        float4 b2 = __ldg((const float4*)(m2 + r2 * DIM + col));
        float4 a3 = __ldg((const float4*)(m1 + r3 * DIM + col));
        float4 b3 = __ldg((const float4*)(m2 + r3 * DIM + col));
        sR = f4add(sR, f4add(f4add(a0, a1), f4add(a2, a3)));
        sT = f4add(sT, f4add(f4add(b0, b1), f4add(b2, b3)));
    }
    for (; r < cnt; r++) {
        int r0 = __ldg(&g_order[start + r]);
        sR = f4add(sR, __ldg((const float4*)(m1 + r0 * DIM + col)));
        sT = f4add(sT, __ldg((const float4*)(m2 + r0 * DIM + col)));
    }

    float inv = 1.0f / (float)(cnt > 0 ? cnt : 1);
    float4 mR = f4scale(sR, inv);
    float4 mT = f4scale(sT, inv);
    float4 ct = f4scale(f4add(mR, mT), 0.5f);

    int o = c * DIM + col;
    *(float4*)(g_meanR + o) = mR;
    *(float4*)(g_meanT + o) = mT;
    *(float4*)(g_cent  + o) = ct;

    // norm partials for this column tile
    float nr = f4dot(mR, mR);
    float nt = f4dot(mT, mT);
    float nc2 = f4dot(ct, ct);
#pragma unroll
    for (int off = 16; off; off >>= 1) {
        nr  += __shfl_down_sync(0xffffffffu, nr, off);
        nt  += __shfl_down_sync(0xffffffffu, nt, off);
        nc2 += __shfl_down_sync(0xffffffffu, nc2, off);
    }
    __shared__ float sred[3][4];
    int wid = threadIdx.x >> 5, lane = threadIdx.x & 31;
    if (lane == 0) { sred[0][wid] = nr; sred[1][wid] = nt; sred[2][wid] = nc2; }
    __syncthreads();
    if (threadIdx.x == 0) {
        g_npart[0][c][tile] = sred[0][0] + sred[0][1] + sred[0][2] + sred[0][3];
        g_npart[1][c][tile] = sred[1][0] + sred[1][1] + sred[1][2] + sred[1][3];
        g_npart[2][c][tile] = sred[2][0] + sred[2][1] + sred[2][2] + sred[2][3];
    }
}

// ---------------- Kernel 3: split-K Gram partials -------------------------
// Grid (4,4,KZ) = 1024 blocks of 64 threads (64K threads). Tile: 32 a-rows x
// 32 b-rows, micro-tile 4x4 per thread, k-chunk KCH=32. Shared padded ->
// conflict-free broadcast loads. 12 LDS per 32 FMAs inner ratio.
// Deterministic (per-chunk partials, no atomics).
__global__ void __launch_bounds__(64) k_gram() {
    __shared__ float shR[32][KCH + 1];
    __shared__ float shT[32][KCH + 1];
    __shared__ float shC[32][KCH + 1];
    int az = blockIdx.x * 32, bz = blockIdx.y * 32;
    int kz = blockIdx.z * KCH;
    int tid = threadIdx.x;

    for (int i = tid; i < 32 * KCH; i += 64) {
        int rr = i >> 5, k = i & (KCH - 1);
        shR[rr][k] = g_meanR[(az + rr) * DIM + kz + k];
        shT[rr][k] = g_meanT[(az + rr) * DIM + kz + k];
        shC[rr][k] = g_cent [(bz + rr) * DIM + kz + k];
    }
    __syncthreads();

    int tx = tid & 7, ty = tid >> 3;
    int a0 = ty * 4, b0 = tx * 4;
    float s1[4][4] = {};
    float s2[4][4] = {};
#pragma unroll 4
    for (int k = 0; k < KCH; k++) {
        float ar[4], at[4], cb[4];
#pragma unroll
        for (int i = 0; i < 4; i++) {
            ar[i] = shR[a0 + i][k];
            at[i] = shT[a0 + i][k];
            cb[i] = shC[b0 + i][k];
        }
#pragma unroll
        for (int i = 0; i < 4; i++)
#pragma unroll
            for (int j = 0; j < 4; j++) {
                s1[i][j] += ar[i] * cb[j];
                s2[i][j] += at[i] * cb[j];
            }
    }
    float* o1 = &g_S1p[blockIdx.z][0];
    float* o2 = &g_S2p[blockIdx.z][0];
#pragma unroll
    for (int i = 0; i < 4; i++)
#pragma unroll
        for (int j = 0; j < 4; j++) {
            int idx = (az + a0 + i) * NC + (bz + b0 + j);
            o1[idx] = s1[i][j];
            o2[idx] = s2[i][j];
        }
}

// ---------------- Kernel 4: per-pair loss terms + block partial sums ------
// 64 blocks x 256 threads, one (a,b) class pair per thread.
__global__ void __launch_bounds__(256) k_pair() {
    int p = blockIdx.x * 256 + threadIdx.x;
    int a = p >> 7, b = p & 127;

    float s1 = 0.f, s2 = 0.f;
#pragma unroll 8
    for (int z = 0; z < KZ; z++) {
        s1 += g_S1p[z][p];
        s2 += g_S2p[z][p];
    }
    float nr = g_npart[0][a][0] + g_npart[0][a][1] + g_npart[0][a][2] + g_npart[0][a][3];
    float nt = g_npart[1][a][0] + g_npart[1][a][1] + g_npart[1][a][2] + g_npart[1][a][3];
    float nn = g_npart[2][b][0] + g_npart[2][b][1] + g_npart[2][b][2] + g_npart[2][b][3];

    float sq1 = fmaxf(nr + nn - 2.f * s1, 1e-12f);
    float sq2 = fmaxf(nt + nn - 2.f * s2, 1e-12f);

    float t1, t2;
    if (a == b) {
        // label==1: dist^2 == clamped squared distance (dist = sqrt(clamp))
        t1 = sq1;
        t2 = sq2;
    } else {
        float dd1 = sqrtf(sqrtf(sq1) + 1e-10f);
        float dd2 = sqrtf(sqrtf(sq2) + 1e-10f);
        float r1 = fmaxf(MARGIN - dd1, 0.f);
        float r2 = fmaxf(MARGIN - dd2, 0.f);
        t1 = r1 * r1;
        t2 = r2 * r2;
    }
    float wgt = (float)g_count[a] * (float)g_count[b];
    float v = wgt * (t1 + t2);

    // deterministic block reduce
#pragma unroll
    for (int off = 16; off; off >>= 1) v += __shfl_down_sync(0xffffffffu, v, off);
    __shared__ float s[8];
    int wid = threadIdx.x >> 5, lane = threadIdx.x & 31;
    if (lane == 0) s[wid] = v;
    __syncthreads();
    if (threadIdx.x == 0) {
        float tt = 0.f;
#pragma unroll
        for (int i = 0; i < 8; i++) tt += s[i];
        g_lpart[blockIdx.x] = tt;
    }
}

// ---------------- Kernel 5: final reduce to scalar ------------------------
__global__ void __launch_bounds__(64) k_final(float* __restrict__ out) {
    int t = threadIdx.x;
    float v = g_lpart[t];
#pragma unroll
    for (int off = 16; off; off >>= 1) v += __shfl_down_sync(0xffffffffu, v, off);
    __shared__ float s[2];
    if ((t & 31) == 0) s[t >> 5] = v;
    __syncthreads();
    if (t == 0) out[0] = (s[0] + s[1]) * (1.0f / ((float)NROWS * (float)NROWS));
}

// ---------------- launch ---------------------------------------------------
extern "C" void kernel_launch(void* const* d_in, const int* in_sizes, int n_in,
                              void* d_out, int out_size) {
    const float* m1 = (const float*)d_in[0];
    const float* m2 = (const float*)d_in[1];
    const int* tgt = (const int*)d_in[2];

    k_sort<<<1, 1024>>>(tgt);
    k_mean<<<dim3(NC, NTILE), 128>>>(m1, m2);
    k_gram<<<dim3(4, 4, KZ), 64>>>();
    k_pair<<<64, 256>>>();
    k_final<<<1, 64>>>((float*)d_out);
}

// round 3
// speedup vs baseline: 1.3845x; 1.3845x over previous
#include <cuda_runtime.h>

#define NROWS 4096
#define DIM   2048
#define NC    128
#define NTILE 4            // column tiles in k_mean (512 cols each)
#define KZ    32           // K-chunks in gram
#define KCH   64           // chunk size, KZ*KCH == DIM
#define MARGIN 0.5f

typedef unsigned long long u64;

// ---------------- persistent scratch (static device globals; no allocs) ----
__device__ int   g_order[NROWS];
__device__ int   g_start[NC];
__device__ int   g_count[NC];
__device__ float g_meanR[NC * DIM];
__device__ float g_meanT[NC * DIM];
__device__ float g_cent [NC * DIM];
__device__ float g_npart[3][NC][NTILE];   // [0]=|meanR|^2, [1]=|meanT|^2, [2]=|cent|^2
__device__ float g_S1p[KZ][NC * NC];      // meanR . cent^T partials per k-chunk
__device__ float g_S2p[KZ][NC * NC];      // meanT . cent^T partials per k-chunk
__device__ float g_lpart[NC];

// ---------------- helpers ---------------------------------------------------
__device__ __forceinline__ float4 f4add(float4 a, float4 b) {
    return make_float4(a.x + b.x, a.y + b.y, a.z + b.z, a.w + b.w);
}
__device__ __forceinline__ float4 f4scale(float4 a, float s) {
    return make_float4(a.x * s, a.y * s, a.z * s, a.w * s);
}
__device__ __forceinline__ float f4dot(float4 a, float4 b) {
    return a.x * b.x + a.y * b.y + a.z * b.z + a.w * b.w;
}
// packed dual-FMA: acc(2xf32) += a(2xf32) * b(2xf32)  (Blackwell f32x2 pipe)
__device__ __forceinline__ void fma2(u64& acc, u64 a, u64 b) {
    asm("fma.rn.f32x2 %0, %1, %2, %0;" : "+l"(acc) : "l"(a), "l"(b));
}
__device__ __forceinline__ float unpack_sum(u64 v) {
    return __uint_as_float((unsigned)(v & 0xffffffffu)) +
           __uint_as_float((unsigned)(v >> 32));
}

// ---------------- Kernel 1: deterministic stable counting sort ------------
__global__ void __launch_bounds__(1024) k_sort(const int* __restrict__ tgt) {
    __shared__ int hist[32][NC];
    __shared__ int totals[NC];
    __shared__ int cinc[NC];
    int tid = threadIdx.x;
    for (int i = tid; i < 32 * NC; i += 1024) (&hist[0][0])[i] = 0;
    __syncthreads();

    int w = tid >> 5, lane = tid & 31;
    int myc[4], myr[4];
#pragma unroll
    for (int s = 0; s < 4; s++) {
        int idx = w * 128 + s * 32 + lane;
        int c = tgt[idx];
        unsigned mk = __match_any_sync(0xffffffffu, c);
        int leader = __ffs(mk) - 1;
        int lr = __popc(mk & ((1u << lane) - 1u));
        int prev = hist[w][c];
        __syncwarp();
        if (lane == leader) hist[w][c] = prev + __popc(mk);
        __syncwarp();
        myc[s] = c;
        myr[s] = prev + lr;
    }
    __syncthreads();

    if (tid < NC) {
        int run = 0;
#pragma unroll 4
        for (int k = 0; k < 32; k++) {
            int v = hist[k][tid];
            hist[k][tid] = run;
            run += v;
        }
        totals[tid] = run;
        cinc[tid] = run;
    }
    __syncthreads();

    for (int off = 1; off < NC; off <<= 1) {
        int v = 0;
        if (tid < NC && tid >= off) v = cinc[tid - off];
        __syncthreads();
        if (tid < NC) cinc[tid] += v;
        __syncthreads();
    }
    if (tid < NC) {
        g_start[tid] = cinc[tid] - totals[tid];
        g_count[tid] = totals[tid];
    }

#pragma unroll
    for (int s = 0; s < 4; s++) {
        int c = myc[s];
        int pos = (cinc[c] - totals[c]) + hist[w][c] + myr[s];
        g_order[pos] = w * 128 + s * 32 + lane;
    }
}

// ---------------- Kernel 2: per-class means + centers + norm partials -----
__global__ void __launch_bounds__(128) k_mean(const float* __restrict__ m1,
                                              const float* __restrict__ m2) {
    int c = blockIdx.x;
    int tile = blockIdx.y;
    int col = tile * 512 + threadIdx.x * 4;
    int start = g_start[c];
    int cnt = g_count[c];

    float4 sR = make_float4(0.f, 0.f, 0.f, 0.f);
    float4 sT = make_float4(0.f, 0.f, 0.f, 0.f);

    int r = 0;
    for (; r + 4 <= cnt; r += 4) {
        int r0 = __ldg(&g_order[start + r]);
        int r1 = __ldg(&g_order[start + r + 1]);
        int r2 = __ldg(&g_order[start + r + 2]);
        int r3 = __ldg(&g_order[start + r + 3]);
        float4 a0 = __ldg((const float4*)(m1 + r0 * DIM + col));
        float4 b0 = __ldg((const float4*)(m2 + r0 * DIM + col));
        float4 a1 = __ldg((const float4*)(m1 + r1 * DIM + col));
        float4 b1 = __ldg((const float4*)(m2 + r1 * DIM + col));
        float4 a2 = __ldg((const float4*)(m1 + r2 * DIM + col));
        float4 b2 = __ldg((const float4*)(m2 + r2 * DIM + col));
        float4 a3 = __ldg((const float4*)(m1 + r3 * DIM + col));
        float4 b3 = __ldg((const float4*)(m2 + r3 * DIM + col));
        sR = f4add(sR, f4add(f4add(a0, a1), f4add(a2, a3)));
        sT = f4add(sT, f4add(f4add(b0, b1), f4add(b2, b3)));
    }
    for (; r < cnt; r++) {
        int r0 = __ldg(&g_order[start + r]);
        sR = f4add(sR, __ldg((const float4*)(m1 + r0 * DIM + col)));
        sT = f4add(sT, __ldg((const float4*)(m2 + r0 * DIM + col)));
    }

    float inv = 1.0f / (float)(cnt > 0 ? cnt : 1);
    float4 mR = f4scale(sR, inv);
    float4 mT = f4scale(sT, inv);
    float4 ct = f4scale(f4add(mR, mT), 0.5f);

    int o = c * DIM + col;
    *(float4*)(g_meanR + o) = mR;
    *(float4*)(g_meanT + o) = mT;
    *(float4*)(g_cent  + o) = ct;

    float nr = f4dot(mR, mR);
    float nt = f4dot(mT, mT);
    float nc2 = f4dot(ct, ct);
#pragma unroll
    for (int off = 16; off; off >>= 1) {
        nr  += __shfl_down_sync(0xffffffffu, nr, off);
        nt  += __shfl_down_sync(0xffffffffu, nt, off);
        nc2 += __shfl_down_sync(0xffffffffu, nc2, off);
    }
    __shared__ float sred[3][4];
    int wid = threadIdx.x >> 5, lane = threadIdx.x & 31;
    if (lane == 0) { sred[0][wid] = nr; sred[1][wid] = nt; sred[2][wid] = nc2; }
    __syncthreads();
    if (threadIdx.x == 0) {
        g_npart[0][c][tile] = sred[0][0] + sred[0][1] + sred[0][2] + sred[0][3];
        g_npart[1][c][tile] = sred[1][0] + sred[1][1] + sred[1][2] + sred[1][3];
        g_npart[2][c][tile] = sred[2][0] + sred[2][1] + sred[2][2] + sred[2][3];
    }
}

// ---------------- Kernel 3: split-K Gram partials (packed f32x2 FMA) ------
// Grid (4,4,KZ) = 512 blocks of 64 threads. Tile 32a x 32b, micro-tile 4x4
// per thread with INTERLEAVED mapping: thread (ty,tx) owns a-rows {ty+8i},
// b-cols {tx+8j}. Accumulators are f32x2 pairs over (even k, odd k);
// operands loaded directly as LDS.64 u64 -> zero packing overhead.
// Row stride 68 floats => consecutive rows 4 banks apart => conflict-free.
__global__ void __launch_bounds__(64) k_gram() {
    __shared__ float shR[32][KCH + 4];
    __shared__ float shT[32][KCH + 4];
    __shared__ float shC[32][KCH + 4];
    int az = blockIdx.x * 32, bz = blockIdx.y * 32;
    int kz = blockIdx.z * KCH;
    int tid = threadIdx.x;

    // cooperative tile load: 32 rows x 16 float4 per tile, 8 float4/thread
#pragma unroll
    for (int t = 0; t < 8; t++) {
        int f = tid + t * 64;
        int row = f >> 4, c4 = (f & 15) * 4;
        *(float4*)&shR[row][c4] = *(const float4*)&g_meanR[(az + row) * DIM + kz + c4];
        *(float4*)&shT[row][c4] = *(const float4*)&g_meanT[(az + row) * DIM + kz + c4];
        *(float4*)&shC[row][c4] = *(const float4*)&g_cent [(bz + row) * DIM + kz + c4];
    }
    __syncthreads();

    int tx = tid & 7, ty = tid >> 3;
    u64 s1[4][4] = {};
    u64 s2[4][4] = {};

#pragma unroll 4
    for (int kq = 0; kq < KCH / 4; kq++) {
        u64 arL[4], arH[4], atL[4], atH[4], cbL[4], cbH[4];
#pragma unroll
        for (int i = 0; i < 4; i++) {
            const u64* pr = (const u64*)&shR[ty + 8 * i][kq * 4];
            const u64* pt = (const u64*)&shT[ty + 8 * i][kq * 4];
            const u64* pc = (const u64*)&shC[tx + 8 * i][kq * 4];
            arL[i] = pr[0]; arH[i] = pr[1];
            atL[i] = pt[0]; atH[i] = pt[1];
            cbL[i] = pc[0]; cbH[i] = pc[1];
        }
#pragma unroll
        for (int i = 0; i < 4; i++)
#pragma unroll
            for (int j = 0; j < 4; j++) {
                fma2(s1[i][j], arL[i], cbL[j]);
                fma2(s1[i][j], arH[i], cbH[j]);
                fma2(s2[i][j], atL[i], cbL[j]);
                fma2(s2[i][j], atH[i], cbH[j]);
            }
    }

    float* o1 = &g_S1p[blockIdx.z][0];
    float* o2 = &g_S2p[blockIdx.z][0];
#pragma unroll
    for (int i = 0; i < 4; i++)
#pragma unroll
        for (int j = 0; j < 4; j++) {
            int idx = (az + ty + 8 * i) * NC + (bz + tx + 8 * j);
            o1[idx] = unpack_sum(s1[i][j]);
            o2[idx] = unpack_sum(s2[i][j]);
        }
}

// ---------------- Kernel 4: per-pair loss + per-class partial sums --------
// 128 blocks (one per class a) x 128 threads (one per class b).
__global__ void __launch_bounds__(128) k_pair() {
    int a = blockIdx.x, b = threadIdx.x;
    int p = a * NC + b;

    float s1 = 0.f, s2 = 0.f;
#pragma unroll
    for (int z = 0; z < KZ; z++) {
        s1 += g_S1p[z][p];
        s2 += g_S2p[z][p];
    }
    float nr = g_npart[0][a][0] + g_npart[0][a][1] + g_npart[0][a][2] + g_npart[0][a][3];
    float nt = g_npart[1][a][0] + g_npart[1][a][1] + g_npart[1][a][2] + g_npart[1][a][3];
    float nn = g_npart[2][b][0] + g_npart[2][b][1] + g_npart[2][b][2] + g_npart[2][b][3];

    float sq1 = fmaxf(nr + nn - 2.f * s1, 1e-12f);
    float sq2 = fmaxf(nt + nn - 2.f * s2, 1e-12f);

    float t1, t2;
    if (a == b) {
        t1 = sq1;          // label==1: dist^2 == clamped squared distance
        t2 = sq2;
    } else {
        float dd1 = sqrtf(sqrtf(sq1) + 1e-10f);
        float dd2 = sqrtf(sqrtf(sq2) + 1e-10f);
        float r1 = fmaxf(MARGIN - dd1, 0.f);
        float r2 = fmaxf(MARGIN - dd2, 0.f);
        t1 = r1 * r1;
        t2 = r2 * r2;
    }
    float wgt = (float)g_count[a] * (float)g_count[b];
    float v = wgt * (t1 + t2);

#pragma unroll
    for (int off = 16; off; off >>= 1) v += __shfl_down_sync(0xffffffffu, v, off);
    __shared__ float s[4];
    int wid = threadIdx.x >> 5, lane = threadIdx.x & 31;
    if (lane == 0) s[wid] = v;
    __syncthreads();
    if (threadIdx.x == 0)
        g_lpart[a] = s[0] + s[1] + s[2] + s[3];
}

// ---------------- Kernel 5: final reduce to scalar ------------------------
__global__ void __launch_bounds__(128) k_final(float* __restrict__ out) {
    int t = threadIdx.x;
    float v = g_lpart[t];
#pragma unroll
    for (int off = 16; off; off >>= 1) v += __shfl_down_sync(0xffffffffu, v, off);
    __shared__ float s[4];
    if ((t & 31) == 0) s[t >> 5] = v;
    __syncthreads();
    if (t == 0)
        out[0] = (s[0] + s[1] + s[2] + s[3]) * (1.0f / ((float)NROWS * (float)NROWS));
}

// ---------------- launch ---------------------------------------------------
extern "C" void kernel_launch(void* const* d_in, const int* in_sizes, int n_in,
                              void* d_out, int out_size) {
    const float* m1 = (const float*)d_in[0];
    const float* m2 = (const float*)d_in[1];
    const int* tgt = (const int*)d_in[2];

    k_sort<<<1, 1024>>>(tgt);
    k_mean<<<dim3(NC, NTILE), 128>>>(m1, m2);
    k_gram<<<dim3(4, 4, KZ), 64>>>();
    k_pair<<<NC, 128>>>();
    k_final<<<1, 128>>>((float*)d_out);
}

// round 9
// speedup vs baseline: 1.6971x; 1.2257x over previous
#include <cuda_runtime.h>

#define NROWS 4096
#define DIM   2048
#define NC    128
#define NTILE 4            // column tiles in k_mean (512 cols each)
#define KZ    16           // K-chunks in gram
#define KCH   128          // chunk size per gram block, KZ*KCH == DIM
#define MARGIN 0.5f

typedef unsigned long long u64;

// ---------------- persistent scratch (static device globals; no allocs) ----
__device__ int   g_count[NC];
__device__ float g_meanR[NC * DIM];
__device__ float g_meanT[NC * DIM];
__device__ float g_cent [NC * DIM];
__device__ float g_npart[3][NC][NTILE];   // [0]=|meanR|^2, [1]=|meanT|^2, [2]=|cent|^2
__device__ float g_S1p[KZ][NC * NC];      // meanR . cent^T partials per k-chunk
__device__ float g_S2p[KZ][NC * NC];      // meanT . cent^T partials per k-chunk
__device__ float g_lpart[NC];
__device__ int   g_done;                   // last-block counter (reset by finisher)

// ---------------- helpers ---------------------------------------------------
__device__ __forceinline__ float4 f4add(float4 a, float4 b) {
    return make_float4(a.x + b.x, a.y + b.y, a.z + b.z, a.w + b.w);
}
__device__ __forceinline__ float4 f4scale(float4 a, float s) {
    return make_float4(a.x * s, a.y * s, a.z * s, a.w * s);
}
__device__ __forceinline__ float f4dot(float4 a, float4 b) {
    return a.x * b.x + a.y * b.y + a.z * b.z + a.w * b.w;
}
// packed dual-FMA: acc(2xf32) += a(2xf32) * b(2xf32)  (Blackwell f32x2 pipe)
__device__ __forceinline__ void fma2(u64& acc, u64 a, u64 b) {
    asm("fma.rn.f32x2 %0, %1, %2, %0;" : "+l"(acc) : "l"(a), "l"(b));
}
__device__ __forceinline__ float unpack_sum(u64 v) {
    return __uint_as_float((unsigned)(v & 0xffffffffu)) +
           __uint_as_float((unsigned)(v >> 32));
}

// ---------------- Kernel 1: per-class means (inline row-selection scan) ----
// Grid (NC, NTILE), 128 threads. Each block scans the 4096 targets (ballot +
// prefix scan -> stable ordered row list in shared), then accumulates its
// class's rows for a 512-col tile. Deterministic, no atomics, no sort kernel.
__global__ void __launch_bounds__(128) k_mean(const float* __restrict__ m1,
                                              const float* __restrict__ m2,
                                              const int* __restrict__ tgt) {
    __shared__ int s_rows[NROWS];
    __shared__ int s_wsum[4];
    __shared__ int s_cnt;
    int c = blockIdx.x;
    int tile = blockIdx.y;
    int tid = threadIdx.x, lane = tid & 31, w = tid >> 5;

    // ---- build stable row list for class c ----
    int base = tid * 32;
    unsigned mask = 0;
#pragma unroll
    for (int i = 0; i < 8; i++) {
        int4 t4 = *(const int4*)&tgt[base + i * 4];
        if (t4.x == c) mask |= 1u << (i * 4 + 0);
        if (t4.y == c) mask |= 1u << (i * 4 + 1);
        if (t4.z == c) mask |= 1u << (i * 4 + 2);
        if (t4.w == c) mask |= 1u << (i * 4 + 3);
    }
    int myn = __popc(mask);
    int inc = myn;
#pragma unroll
    for (int off = 1; off < 32; off <<= 1) {
        int v = __shfl_up_sync(0xffffffffu, inc, off);
        if (lane >= off) inc += v;
    }
    if (lane == 31) s_wsum[w] = inc;
    __syncthreads();
    int woff = 0;
#pragma unroll
    for (int k = 0; k < 4; k++) if (k < w) woff += s_wsum[k];
    if (tid == 0) s_cnt = s_wsum[0] + s_wsum[1] + s_wsum[2] + s_wsum[3];
    int pos = woff + inc - myn;
    unsigned mm = mask;
    while (mm) { int b = __ffs(mm) - 1; mm &= mm - 1; s_rows[pos++] = base + b; }
    __syncthreads();
    int cnt = s_cnt;
    if (tile == 0 && tid == 0) g_count[c] = cnt;

    // ---- accumulate rows (unroll-4: 8 independent 16B loads in flight) ----
    int col = tile * 512 + tid * 4;
    float4 sR = make_float4(0.f, 0.f, 0.f, 0.f);
    float4 sT = make_float4(0.f, 0.f, 0.f, 0.f);

    int r = 0;
    for (; r + 4 <= cnt; r += 4) {
        int r0 = s_rows[r], r1 = s_rows[r + 1], r2 = s_rows[r + 2], r3 = s_rows[r + 3];
        float4 a0 = __ldg((const float4*)(m1 + r0 * DIM + col));
        float4 b0 = __ldg((const float4*)(m2 + r0 * DIM + col));
        float4 a1 = __ldg((const float4*)(m1 + r1 * DIM + col));
        float4 b1 = __ldg((const float4*)(m2 + r1 * DIM + col));
        float4 a2 = __ldg((const float4*)(m1 + r2 * DIM + col));
        float4 b2 = __ldg((const float4*)(m2 + r2 * DIM + col));
        float4 a3 = __ldg((const float4*)(m1 + r3 * DIM + col));
        float4 b3 = __ldg((const float4*)(m2 + r3 * DIM + col));
        sR = f4add(sR, f4add(f4add(a0, a1), f4add(a2, a3)));
        sT = f4add(sT, f4add(f4add(b0, b1), f4add(b2, b3)));
    }
    for (; r < cnt; r++) {
        int r0 = s_rows[r];
        sR = f4add(sR, __ldg((const float4*)(m1 + r0 * DIM + col)));
        sT = f4add(sT, __ldg((const float4*)(m2 + r0 * DIM + col)));
    }

    float inv = 1.0f / (float)(cnt > 0 ? cnt : 1);
    float4 mR = f4scale(sR, inv);
    float4 mT = f4scale(sT, inv);
    float4 ct = f4scale(f4add(mR, mT), 0.5f);

    int o = c * DIM + col;
    *(float4*)(g_meanR + o) = mR;
    *(float4*)(g_meanT + o) = mT;
    *(float4*)(g_cent  + o) = ct;

    // ---- norm partials for this tile ----
    float nr = f4dot(mR, mR);
    float nt = f4dot(mT, mT);
    float nc2 = f4dot(ct, ct);
#pragma unroll
    for (int off = 16; off; off >>= 1) {
        nr  += __shfl_down_sync(0xffffffffu, nr, off);
        nt  += __shfl_down_sync(0xffffffffu, nt, off);
        nc2 += __shfl_down_sync(0xffffffffu, nc2, off);
    }
    __shared__ float sred[3][4];
    if (lane == 0) { sred[0][w] = nr; sred[1][w] = nt; sred[2][w] = nc2; }
    __syncthreads();
    if (tid == 0) {
        g_npart[0][c][tile] = sred[0][0] + sred[0][1] + sred[0][2] + sred[0][3];
        g_npart[1][c][tile] = sred[1][0] + sred[1][1] + sred[1][2] + sred[1][3];
        g_npart[2][c][tile] = sred[2][0] + sred[2][1] + sred[2][2] + sred[2][3];
    }
}

// ---------------- Kernel 2: split-K Gram partials (packed f32x2 FMA) ------
// Grid (4,4,KZ) = 256 blocks of 128 threads. Tile 32a x 32b, micro-tile 2x4
// per thread (interleaved rows ty+16i, cols tx+8j). KCH=128 processed as two
// 64-wide smem sub-chunks (26 KB smem). Stride-68 rows -> conflict-free
// LDS.64 broadcast loads. Deterministic per-chunk partials.
__global__ void __launch_bounds__(128) k_gram() {
    __shared__ float shR[32][68];
    __shared__ float shT[32][68];
    __shared__ float shC[32][68];
    int az = blockIdx.x * 32, bz = blockIdx.y * 32;
    int tid = threadIdx.x;
    int tx = tid & 7, ty = tid >> 3;

    u64 s1[2][4] = {};
    u64 s2[2][4] = {};

#pragma unroll
    for (int s = 0; s < 2; s++) {
        int kz = blockIdx.z * KCH + s * 64;
        if (s) __syncthreads();   // protect prior sub-chunk reads
#pragma unroll
        for (int t = 0; t < 4; t++) {
            int f = tid + t * 128;
            int row = f >> 4, c4 = (f & 15) * 4;
            *(float4*)&shR[row][c4] = *(const float4*)&g_meanR[(az + row) * DIM + kz + c4];
            *(float4*)&shT[row][c4] = *(const float4*)&g_meanT[(az + row) * DIM + kz + c4];
            *(float4*)&shC[row][c4] = *(const float4*)&g_cent [(bz + row) * DIM + kz + c4];
        }
        __syncthreads();

#pragma unroll 8
        for (int kq = 0; kq < 32; kq++) {
            u64 ar0 = *(const u64*)&shR[ty     ][kq * 2];
            u64 ar1 = *(const u64*)&shR[ty + 16][kq * 2];
            u64 at0 = *(const u64*)&shT[ty     ][kq * 2];
            u64 at1 = *(const u64*)&shT[ty + 16][kq * 2];
            u64 cb[4];
#pragma unroll
            for (int j = 0; j < 4; j++) cb[j] = *(const u64*)&shC[tx + 8 * j][kq * 2];
#pragma unroll
            for (int j = 0; j < 4; j++) {
                fma2(s1[0][j], ar0, cb[j]);
                fma2(s1[1][j], ar1, cb[j]);
                fma2(s2[0][j], at0, cb[j]);
                fma2(s2[1][j], at1, cb[j]);
            }
        }
    }

    float* o1 = &g_S1p[blockIdx.z][0];
    float* o2 = &g_S2p[blockIdx.z][0];
#pragma unroll
    for (int i = 0; i < 2; i++)
#pragma unroll
        for (int j = 0; j < 4; j++) {
            int idx = (az + ty + 16 * i) * NC + (bz + tx + 8 * j);
            o1[idx] = unpack_sum(s1[i][j]);
            o2[idx] = unpack_sum(s2[i][j]);
        }
}

// ---------------- Kernel 3: per-pair loss + fused final reduce ------------
// 128 blocks (class a) x 128 threads (class b). Last finishing block
// (deterministic int-atomic counter) reduces the 128 per-class partials in
// fixed order -> bitwise-deterministic scalar. Counter reset for next replay.
__global__ void __launch_bounds__(128) k_pair(float* __restrict__ out) {
    int a = blockIdx.x, b = threadIdx.x;
    int p = a * NC + b;

    float s1 = 0.f, s2 = 0.f;
#pragma unroll
    for (int z = 0; z < KZ; z++) {
        s1 += g_S1p[z][p];
        s2 += g_S2p[z][p];
    }
    float nr = g_npart[0][a][0] + g_npart[0][a][1] + g_npart[0][a][2] + g_npart[0][a][3];
    float nt = g_npart[1][a][0] + g_npart[1][a][1] + g_npart[1][a][2] + g_npart[1][a][3];
    float nn = g_npart[2][b][0] + g_npart[2][b][1] + g_npart[2][b][2] + g_npart[2][b][3];

    float sq1 = fmaxf(nr + nn - 2.f * s1, 1e-12f);
    float sq2 = fmaxf(nt + nn - 2.f * s2, 1e-12f);

    float t1, t2;
    if (a == b) {
        t1 = sq1;          // label==1: dist^2 == clamped squared distance
        t2 = sq2;
    } else {
        float dd1 = sqrtf(sqrtf(sq1) + 1e-10f);
        float dd2 = sqrtf(sqrtf(sq2) + 1e-10f);
        float r1 = fmaxf(MARGIN - dd1, 0.f);
        float r2 = fmaxf(MARGIN - dd2, 0.f);
        t1 = r1 * r1;
        t2 = r2 * r2;
    }
    float wgt = (float)g_count[a] * (float)g_count[b];
    float v = wgt * (t1 + t2);

    // deterministic block reduce -> g_lpart[a]
    int lane = threadIdx.x & 31, w = threadIdx.x >> 5;
#pragma unroll
    for (int off = 16; off; off >>= 1) v += __shfl_down_sync(0xffffffffu, v, off);
    __shared__ float s[4];
    if (lane == 0) s[w] = v;
    __syncthreads();
    if (threadIdx.x == 0)
        g_lpart[a] = s[0] + s[1] + s[2] + s[3];

    // last-block finisher (threadFenceReduction pattern; value-deterministic)
    __threadfence();
    __shared__ int lastv;
    if (threadIdx.x == 0) lastv = atomicAdd(&g_done, 1);
    __syncthreads();
    if (lastv == NC - 1) {
        __threadfence();
        if (threadIdx.x == 0) g_done = 0;   // reset for next graph replay
        float f = *(volatile float*)&g_lpart[threadIdx.x];
#pragma unroll
        for (int off = 16; off; off >>= 1) f += __shfl_down_sync(0xffffffffu, f, off);
        __shared__ float s2f[4];
        if (lane == 0) s2f[w] = f;
        __syncthreads();
        if (threadIdx.x == 0)
            out[0] = (s2f[0] + s2f[1] + s2f[2] + s2f[3]) *
                     (1.0f / ((float)NROWS * (float)NROWS));
    }
}

// ---------------- launch ---------------------------------------------------
extern "C" void kernel_launch(void* const* d_in, const int* in_sizes, int n_in,
                              void* d_out, int out_size) {
    const float* m1 = (const float*)d_in[0];
    const float* m2 = (const float*)d_in[1];
    const int* tgt = (const int*)d_in[2];

    k_mean<<<dim3(NC, NTILE), 128>>>(m1, m2, tgt);
    k_gram<<<dim3(4, 4, KZ), 128>>>();
    k_pair<<<NC, 128>>>((float*)d_out);
}